// round 9
// baseline (speedup 1.0000x reference)
#include <cuda_runtime.h>
#include <cuda_bf16.h>
#include <cstdint>

// ---------------- shapes ----------------
#define NTOK 4096
#define CDIM 1024
#define NEXP 64
#define TOPK 8
#define CAP  1024
#define HS   1024
#define HE   512

// ---------------- helpers ----------------
__device__ __forceinline__ uint32_t smem_u32(const void* p) {
    uint32_t a;
    asm("{ .reg .u64 t; cvta.to.shared.u64 t, %1; cvt.u32.u64 %0, t; }" : "=r"(a) : "l"(p));
    return a;
}
#define CP_ASYNC16(dst, src) \
    asm volatile("cp.async.cg.shared.global [%0], [%1], 16;" :: "r"(dst), "l"(src))
#define CP_COMMIT() asm volatile("cp.async.commit_group;" ::: "memory")
#define CP_WAIT2()  asm volatile("cp.async.wait_group 2;" ::: "memory")

__device__ __forceinline__ void ldm_x4(uint32_t* r, uint32_t addr) {
    asm volatile("ldmatrix.sync.aligned.m8n8.x4.shared.b16 {%0,%1,%2,%3}, [%4];"
        : "=r"(r[0]), "=r"(r[1]), "=r"(r[2]), "=r"(r[3]) : "r"(addr));
}
__device__ __forceinline__ void mma_tf32(float* d, const uint32_t* a, const uint32_t* b) {
    asm volatile(
        "mma.sync.aligned.m16n8k8.row.col.f32.tf32.tf32.f32 "
        "{%0,%1,%2,%3}, {%4,%5,%6,%7}, {%8,%9}, {%0,%1,%2,%3};"
        : "+f"(d[0]), "+f"(d[1]), "+f"(d[2]), "+f"(d[3])
        : "r"(a[0]), "r"(a[1]), "r"(a[2]), "r"(a[3]), "r"(b[0]), "r"(b[1]));
}
__device__ __forceinline__ float to_tf32(float v) {
    uint32_t r;
    asm("cvt.rna.tf32.f32 %0, %1;" : "=r"(r) : "f"(v));
    return __uint_as_float(r);
}

// ---------------- scratch (device globals) ----------------
__device__ float g_xr  [(size_t)NTOK * CDIM];
__device__ float g_sh  [(size_t)NTOK * HS];
__device__ float g_eh  [(size_t)NEXP * CAP * HE];
__device__ float g_eoe [(size_t)NEXP * CAP * CDIM];
__device__ float g_supt[(size_t)(2 * HS) * CDIM];
__device__ float g_sdnt[(size_t)CDIM * HS];
__device__ float g_eupt[(size_t)NEXP * (2 * HE) * CDIM];
__device__ float g_ednt[(size_t)NEXP * CDIM * HE];
__device__ int   g_counts[NEXP];
__device__ int   g_rowidx[NEXP * CAP];
__device__ int   g_slots[NTOK * TOPK];
__device__ float g_wts [NTOK * TOPK];

// ---------------- fused prep: counts zero + all 4 weight transposes ----------------
// z<64: eupt[z]; z<128: ednt[z-64]; z==128: supt; z==129: sdnt (+ zero counts).
// If half>0, output rows (y,g)-interleaved: n<half -> 2n ; else 2(n-half)+1.
__global__ void prep_kernel(const float* __restrict__ sup_w, const float* __restrict__ sdown_w,
                            const float* __restrict__ eup_w, const float* __restrict__ edown_w,
                            float* __restrict__ supt, float* __restrict__ sdnt,
                            float* __restrict__ eupt, float* __restrict__ ednt,
                            int* __restrict__ counts) {
    __shared__ float tile[32][33];
    int z = blockIdx.z;
    const float* in; float* o;
    int K, N, half, nx, ny;
    size_t inoff = 0, outoff = 0;
    if (z < 64) {
        in = eup_w; o = eupt; K = CDIM; N = 2 * HE; half = HE; nx = 32; ny = 32;
        inoff = (size_t)z * CDIM * 2 * HE; outoff = (size_t)z * 2 * HE * CDIM;
    } else if (z < 128) {
        int zz = z - 64;
        in = edown_w; o = ednt; K = HE; N = CDIM; half = 0; nx = 32; ny = 16;
        inoff = (size_t)zz * HE * CDIM; outoff = (size_t)zz * CDIM * HE;
    } else if (z == 128) {
        in = sup_w; o = supt; K = CDIM; N = 2 * HS; half = HS; nx = 64; ny = 32;
    } else {
        in = sdown_w; o = sdnt; K = HS; N = CDIM; half = 0; nx = 32; ny = 32;
        int ft = threadIdx.y * 32 + threadIdx.x;   // FIX: flattened tid covers all 64
        if (blockIdx.x == 0 && blockIdx.y == 0 && ft < NEXP)
            counts[ft] = 0;
    }
    if ((int)blockIdx.x >= nx || (int)blockIdx.y >= ny) return;
    in += inoff; o += outoff;
    int n0 = blockIdx.x * 32, k0 = blockIdx.y * 32;
    int tx = threadIdx.x, ty = threadIdx.y;
    #pragma unroll
    for (int i = 0; i < 32; i += 8)
        tile[ty + i][tx] = in[(size_t)(k0 + ty + i) * N + n0 + tx];
    __syncthreads();
    #pragma unroll
    for (int i = 0; i < 32; i += 8) {
        float v = tile[tx][ty + i];
        int n = n0 + ty + i;
        int nout = (half > 0) ? ((n < half) ? 2 * n : 2 * (n - half) + 1) : n;
        o[(size_t)nout * K + k0 + tx] = to_tf32(v);
    }
}

// ---------------- router: scores, warp-parallel top-8, slot assign, write xr ----------------
__global__ __launch_bounds__(256) void router_kernel(
    const float* __restrict__ x, const float* __restrict__ rw, const float* __restrict__ bias,
    int* __restrict__ counts, int* __restrict__ rowidx,
    int* __restrict__ slots, float* __restrict__ wts, float* __restrict__ xr) {
    int t = blockIdx.x;
    int tid = threadIdx.x;
    __shared__ float xs[CDIM];
    __shared__ float partial[256];
    __shared__ float sc[NEXP];
    __shared__ float sb[NEXP];

    for (int i = tid; i < CDIM; i += 256) xs[i] = x[(size_t)t * CDIM + i];
    __syncthreads();

    int e = tid & 63, part = tid >> 6;
    float acc = 0.f;
    const float* rwp = rw + (size_t)(part * 256) * NEXP + e;
    #pragma unroll 8
    for (int c = 0; c < 256; c++) acc += xs[part * 256 + c] * rwp[(size_t)c * NEXP];
    partial[tid] = acc;
    __syncthreads();
    if (tid < NEXP) {
        float v = partial[tid] + partial[tid + 64] + partial[tid + 128] + partial[tid + 192];
        float s = 1.f / (1.f + __expf(-v));
        sc[tid] = s;
        sb[tid] = s + bias[tid];
    }
    __syncthreads();

    if (tid < 32) {
        float v0 = sb[tid], v1 = sb[tid + 32];
        int eid = 0;
        #pragma unroll
        for (int k = 0; k < TOPK; k++) {
            float m; int me;
            if (v0 >= v1) { m = v0; me = tid; } else { m = v1; me = tid + 32; }
            #pragma unroll
            for (int off = 16; off; off >>= 1) {
                float om = __shfl_down_sync(0xffffffffu, m, off);
                int   oe = __shfl_down_sync(0xffffffffu, me, off);
                if (om > m) { m = om; me = oe; }
            }
            me = __shfl_sync(0xffffffffu, me, 0);
            if (tid == me) v0 = -1e30f;
            if (tid == me - 32) v1 = -1e30f;
            if (tid == k) eid = me;
        }
        float sv = (tid < TOPK) ? sc[eid] : 0.f;
        float ws = sv;
        #pragma unroll
        for (int off = 4; off; off >>= 1) ws += __shfl_down_sync(0xffffffffu, ws, off, 8);
        ws = __shfl_sync(0xffffffffu, ws, 0);
        if (tid < TOPK) {
            int pos  = atomicAdd(&counts[eid], 1);
            int slot = eid * CAP + pos;
            rowidx[slot] = t;
            slots[t * TOPK + tid] = slot;
            wts  [t * TOPK + tid] = sv / ws;
        }
    }

    for (int i = tid; i < CDIM; i += 256)
        xr[(size_t)t * CDIM + i] = to_tf32(xs[i]);
}

// ---------------- tf32 mma.sync GEMM, z-dispatched dual workload ----------------
// CTA tile 128Mx256N, 8 warps of 64x64, Kc=32, 4-stage single-sync cp.async pipeline.
#define ROWB 144
#define A_BYTES 18432
#define STG_BYTES 55296

struct GArgs {
    const float* A; const float* B; float* D; float* H;
    int M, N, K;
    long sAz, sBz, sDz;
    const int* counts; const int* rowidx;
    int nx, ny;
};

__device__ __forceinline__ void issue_stage(
    uint32_t sdst, const float* __restrict__ pA, const float* __restrict__ pB,
    int K, int kcol, int tid, const int* ar) {
    #pragma unroll
    for (int i = 0; i < 4; i++) {
        int id = tid + 256 * i;
        int row = id >> 3, c4 = id & 7;
        uint32_t so = (uint32_t)(row * ROWB + c4 * 16);
        CP_ASYNC16(sdst + so, pA + (size_t)ar[i] * K + kcol + c4 * 4);
    }
    #pragma unroll
    for (int i = 0; i < 8; i++) {
        int id = tid + 256 * i;
        int row = id >> 3, c4 = id & 7;
        uint32_t so = (uint32_t)(row * ROWB + c4 * 16);
        CP_ASYNC16(sdst + A_BYTES + so, pB + (size_t)row * K + kcol + c4 * 4);
    }
}

__global__ __launch_bounds__(256, 1) void gemm_kernel(GArgs g0, GArgs g1, int zsplit) {
    extern __shared__ __align__(128) char smem[];
    GArgs g; int z;
    if ((int)blockIdx.z < zsplit) { g = g0; z = blockIdx.z; }
    else                          { g = g1; z = blockIdx.z - zsplit; }
    if ((int)blockIdx.x >= g.nx || (int)blockIdx.y >= g.ny) return;

    int M = g.M, N = g.N, K = g.K;
    if (g.counts) M = g.counts[z];
    int m0 = blockIdx.y * 128;
    if (m0 >= M) return;
    int n0 = blockIdx.x * 256;
    const float* A = g.A + (size_t)z * g.sAz;
    const float* B = g.B + (size_t)z * g.sBz;

    int tid = threadIdx.x, wid = tid >> 5, lane = tid & 31;
    int wm = (wid & 1) * 64;
    int wn = (wid >> 1) * 64;
    uint32_t sbase = smem_u32(smem);

    const float* pA;
    int ar[4];
    if (g.rowidx) {
        const int* ridx = g.rowidx + (size_t)z * CAP + m0;
        pA = A;
        #pragma unroll
        for (int i = 0; i < 4; i++) ar[i] = ridx[(tid >> 3) + 32 * i];
    } else {
        pA = A + (size_t)m0 * K;
        #pragma unroll
        for (int i = 0; i < 4; i++) ar[i] = (tid >> 3) + 32 * i;
    }
    const float* pB = B + (size_t)n0 * K;

    float acc[4][8][4];
    #pragma unroll
    for (int i = 0; i < 4; i++)
        #pragma unroll
        for (int j = 0; j < 8; j++)
            #pragma unroll
            for (int r = 0; r < 4; r++) acc[i][j][r] = 0.f;

    const int nk = K >> 5;
    issue_stage(sbase,                 pA, pB, K, 0,  tid, ar); CP_COMMIT();
    issue_stage(sbase + STG_BYTES,     pA, pB, K, 32, tid, ar); CP_COMMIT();
    issue_stage(sbase + 2 * STG_BYTES, pA, pB, K, 64, tid, ar); CP_COMMIT();

    int laneA_row = lane & 15;
    int laneA_c   = ((lane >> 4) & 1) * 16;
    int laneB_n   = (lane & 7) + ((lane >> 4) & 1) * 8;
    int laneB_c   = ((lane >> 3) & 1) * 16;

    for (int kc = 0; kc < nk; kc++) {
        CP_WAIT2();
        __syncthreads();
        if (kc + 3 < nk)
            issue_stage(sbase + ((kc + 3) & 3) * STG_BYTES, pA, pB, K, (kc + 3) * 32, tid, ar);
        CP_COMMIT();

        uint32_t sA = sbase + (kc & 3) * STG_BYTES;
        uint32_t sB = sA + A_BYTES;
        #pragma unroll
        for (int s = 0; s < 4; s++) {
            uint32_t a[4][4];
            #pragma unroll
            for (int mi = 0; mi < 4; mi++)
                ldm_x4(a[mi], sA + (uint32_t)((wm + mi * 16 + laneA_row) * ROWB + s * 32 + laneA_c));
            #pragma unroll
            for (int j = 0; j < 4; j++) {
                uint32_t rb[4];
                ldm_x4(rb, sB + (uint32_t)((wn + j * 16 + laneB_n) * ROWB + s * 32 + laneB_c));
                #pragma unroll
                for (int mi = 0; mi < 4; mi++) {
                    mma_tf32(acc[mi][2 * j],     a[mi], rb);
                    mma_tf32(acc[mi][2 * j + 1], a[mi], rb + 2);
                }
            }
        }
    }

    int r0 = lane >> 2, c0 = (lane & 3) * 2;
    if (g.H) {
        int halfN = N >> 1;
        float* H = g.H + (size_t)z * g.sDz;
        #pragma unroll
        for (int mi = 0; mi < 4; mi++) {
            #pragma unroll
            for (int ni = 0; ni < 8; ni++) {
                int row = m0 + wm + mi * 16 + r0;
                int p = (n0 + wn + ni * 8 + c0) >> 1;
                float y0 = acc[mi][ni][0], gg0 = acc[mi][ni][1];
                float y1 = acc[mi][ni][2], gg1 = acc[mi][ni][3];
                H[(size_t)row * halfN + p]       = to_tf32(y0 * gg0 / (1.f + __expf(-gg0)));
                H[(size_t)(row + 8) * halfN + p] = to_tf32(y1 * gg1 / (1.f + __expf(-gg1)));
            }
        }
    } else {
        float* D = g.D + (size_t)z * g.sDz;
        #pragma unroll
        for (int mi = 0; mi < 4; mi++) {
            #pragma unroll
            for (int ni = 0; ni < 8; ni++) {
                int row = m0 + wm + mi * 16 + r0;
                int col = n0 + wn + ni * 8 + c0;
                *(float2*)(D + (size_t)row * N + col) = make_float2(acc[mi][ni][0], acc[mi][ni][1]);
                *(float2*)(D + (size_t)(row + 8) * N + col) = make_float2(acc[mi][ni][2], acc[mi][ni][3]);
            }
        }
    }
}

// ---------------- combine ----------------
__global__ __launch_bounds__(256) void combine_kernel(
    const float* __restrict__ oe, const int* __restrict__ slots,
    const float* __restrict__ wts, float* __restrict__ out) {
    int t = blockIdx.x;
    int c = threadIdx.x * 4;
    int sl[TOPK]; float ww[TOPK];
    #pragma unroll
    for (int k = 0; k < TOPK; k++) { sl[k] = slots[t * TOPK + k]; ww[k] = wts[t * TOPK + k]; }
    float4 acc = *(float4*)(out + (size_t)t * CDIM + c);
    #pragma unroll
    for (int k = 0; k < TOPK; k++) {
        float4 v = *(const float4*)(oe + (size_t)sl[k] * CDIM + c);
        acc.x += ww[k] * v.x; acc.y += ww[k] * v.y;
        acc.z += ww[k] * v.z; acc.w += ww[k] * v.w;
    }
    *(float4*)(out + (size_t)t * CDIM + c) = acc;
}

// ---------------- launch ----------------
extern "C" void kernel_launch(void* const* d_in, const int* in_sizes, int n_in,
                              void* d_out, int out_size) {
    const float* x       = (const float*)d_in[0];
    const float* rw      = (const float*)d_in[1];
    const float* bias    = (const float*)d_in[2];
    const float* sup_w   = (const float*)d_in[3];
    const float* sdown_w = (const float*)d_in[4];
    const float* eup_w   = (const float*)d_in[5];
    const float* edown_w = (const float*)d_in[6];
    float* out = (float*)d_out;
    (void)in_sizes; (void)n_in; (void)out_size;

    float *xr, *sh, *eh, *eoe, *supt, *sdnt, *eupt, *ednt, *wts;
    int *counts, *rowidx, *slots;
    cudaGetSymbolAddress((void**)&xr, g_xr);
    cudaGetSymbolAddress((void**)&sh, g_sh);
    cudaGetSymbolAddress((void**)&eh, g_eh);
    cudaGetSymbolAddress((void**)&eoe, g_eoe);
    cudaGetSymbolAddress((void**)&supt, g_supt);
    cudaGetSymbolAddress((void**)&sdnt, g_sdnt);
    cudaGetSymbolAddress((void**)&eupt, g_eupt);
    cudaGetSymbolAddress((void**)&ednt, g_ednt);
    cudaGetSymbolAddress((void**)&counts, g_counts);
    cudaGetSymbolAddress((void**)&rowidx, g_rowidx);
    cudaGetSymbolAddress((void**)&slots, g_slots);
    cudaGetSymbolAddress((void**)&wts, g_wts);

    cudaFuncSetAttribute(gemm_kernel, cudaFuncAttributeMaxDynamicSharedMemorySize, 4 * STG_BYTES);
    const int gsmem = 4 * STG_BYTES;

    // 1. prep (counts zero + all transposes) and routing
    prep_kernel<<<dim3(64, 32, 130), dim3(32, 8)>>>(
        sup_w, sdown_w, eup_w, edown_w, supt, sdnt, eupt, ednt, counts);
    router_kernel<<<NTOK, 256>>>(x, rw, bias, counts, rowidx, slots, wts, xr);

    // 2. UP: expert-up (gather + fused swiglu) merged with shared-up (fused swiglu)
    GArgs up0 = { xr, eupt, nullptr, eh, CAP, 2 * HE, CDIM,
                  0, (long)(2 * HE) * CDIM, (long)CAP * HE, counts, rowidx,
                  (2 * HE) / 256, CAP / 128 };
    GArgs up1 = { xr, supt, nullptr, sh, NTOK, 2 * HS, CDIM,
                  0, 0, 0, nullptr, nullptr,
                  (2 * HS) / 256, NTOK / 128 };
    gemm_kernel<<<dim3(8, 32, 65), 256, gsmem>>>(up0, up1, 64);

    // 3. DOWN: expert-down merged with shared-down (writes out)
    GArgs dn0 = { eh, ednt, eoe, nullptr, CAP, CDIM, HE,
                  (long)CAP * HE, (long)CDIM * HE, (long)CAP * CDIM, counts, nullptr,
                  CDIM / 256, CAP / 128 };
    GArgs dn1 = { sh, sdnt, out, nullptr, NTOK, CDIM, HS,
                  0, 0, 0, nullptr, nullptr,
                  CDIM / 256, NTOK / 128 };
    gemm_kernel<<<dim3(4, 32, 65), 256, gsmem>>>(dn0, dn1, 64);

    // 4. combine
    combine_kernel<<<NTOK, 256>>>(eoe, slots, wts, out);
}

// round 10
// speedup vs baseline: 1.0833x; 1.0833x over previous
#include <cuda_runtime.h>
#include <cuda_bf16.h>
#include <cstdint>

// ---------------- shapes ----------------
#define NTOK 4096
#define CDIM 1024
#define NEXP 64
#define TOPK 8
#define CAP  1024
#define HS   1024
#define HE   512

// ---------------- helpers ----------------
__device__ __forceinline__ uint32_t smem_u32(const void* p) {
    uint32_t a;
    asm("{ .reg .u64 t; cvta.to.shared.u64 t, %1; cvt.u32.u64 %0, t; }" : "=r"(a) : "l"(p));
    return a;
}
#define CP_ASYNC16(dst, src) \
    asm volatile("cp.async.cg.shared.global [%0], [%1], 16;" :: "r"(dst), "l"(src))
#define CP_COMMIT() asm volatile("cp.async.commit_group;" ::: "memory")
#define CP_WAIT1()  asm volatile("cp.async.wait_group 1;" ::: "memory")

__device__ __forceinline__ void ldm_x4(uint32_t* r, uint32_t addr) {
    asm volatile("ldmatrix.sync.aligned.m8n8.x4.shared.b16 {%0,%1,%2,%3}, [%4];"
        : "=r"(r[0]), "=r"(r[1]), "=r"(r[2]), "=r"(r[3]) : "r"(addr));
}
__device__ __forceinline__ void mma_tf32(float* d, const uint32_t* a, const uint32_t* b) {
    asm volatile(
        "mma.sync.aligned.m16n8k8.row.col.f32.tf32.tf32.f32 "
        "{%0,%1,%2,%3}, {%4,%5,%6,%7}, {%8,%9}, {%0,%1,%2,%3};"
        : "+f"(d[0]), "+f"(d[1]), "+f"(d[2]), "+f"(d[3])
        : "r"(a[0]), "r"(a[1]), "r"(a[2]), "r"(a[3]), "r"(b[0]), "r"(b[1]));
}
__device__ __forceinline__ float to_tf32(float v) {
    uint32_t r;
    asm("cvt.rna.tf32.f32 %0, %1;" : "=r"(r) : "f"(v));
    return __uint_as_float(r);
}

// ---------------- scratch (device globals) ----------------
__device__ float g_xr  [(size_t)NTOK * CDIM];
__device__ float g_sh  [(size_t)NTOK * HS];
__device__ float g_eh  [(size_t)NEXP * CAP * HE];
__device__ float g_eoe [(size_t)NEXP * CAP * CDIM];
__device__ float g_supt[(size_t)(2 * HS) * CDIM];
__device__ float g_sdnt[(size_t)CDIM * HS];
__device__ float g_eupt[(size_t)NEXP * (2 * HE) * CDIM];
__device__ float g_ednt[(size_t)NEXP * CDIM * HE];
__device__ int   g_counts[NEXP];
__device__ int   g_rowidx[NEXP * CAP];
__device__ int   g_slots[NTOK * TOPK];
__device__ float g_wts [NTOK * TOPK];

// ---------------- fused prep: counts zero + all 4 weight transposes ----------------
__global__ void prep_kernel(const float* __restrict__ sup_w, const float* __restrict__ sdown_w,
                            const float* __restrict__ eup_w, const float* __restrict__ edown_w,
                            float* __restrict__ supt, float* __restrict__ sdnt,
                            float* __restrict__ eupt, float* __restrict__ ednt,
                            int* __restrict__ counts) {
    __shared__ float tile[32][33];
    int z = blockIdx.z;
    const float* in; float* o;
    int K, N, half, nx, ny;
    size_t inoff = 0, outoff = 0;
    if (z < 64) {
        in = eup_w; o = eupt; K = CDIM; N = 2 * HE; half = HE; nx = 32; ny = 32;
        inoff = (size_t)z * CDIM * 2 * HE; outoff = (size_t)z * 2 * HE * CDIM;
    } else if (z < 128) {
        int zz = z - 64;
        in = edown_w; o = ednt; K = HE; N = CDIM; half = 0; nx = 32; ny = 16;
        inoff = (size_t)zz * HE * CDIM; outoff = (size_t)zz * CDIM * HE;
    } else if (z == 128) {
        in = sup_w; o = supt; K = CDIM; N = 2 * HS; half = HS; nx = 64; ny = 32;
    } else {
        in = sdown_w; o = sdnt; K = HS; N = CDIM; half = 0; nx = 32; ny = 32;
        int ft = threadIdx.y * 32 + threadIdx.x;
        if (blockIdx.x == 0 && blockIdx.y == 0 && ft < NEXP)
            counts[ft] = 0;
    }
    if ((int)blockIdx.x >= nx || (int)blockIdx.y >= ny) return;
    in += inoff; o += outoff;
    int n0 = blockIdx.x * 32, k0 = blockIdx.y * 32;
    int tx = threadIdx.x, ty = threadIdx.y;
    #pragma unroll
    for (int i = 0; i < 32; i += 8)
        tile[ty + i][tx] = in[(size_t)(k0 + ty + i) * N + n0 + tx];
    __syncthreads();
    #pragma unroll
    for (int i = 0; i < 32; i += 8) {
        float v = tile[tx][ty + i];
        int n = n0 + ty + i;
        int nout = (half > 0) ? ((n < half) ? 2 * n : 2 * (n - half) + 1) : n;
        o[(size_t)nout * K + k0 + tx] = to_tf32(v);
    }
}

// ---------------- router ----------------
__global__ __launch_bounds__(256) void router_kernel(
    const float* __restrict__ x, const float* __restrict__ rw, const float* __restrict__ bias,
    int* __restrict__ counts, int* __restrict__ rowidx,
    int* __restrict__ slots, float* __restrict__ wts, float* __restrict__ xr) {
    int t = blockIdx.x;
    int tid = threadIdx.x;
    __shared__ float xs[CDIM];
    __shared__ float partial[256];
    __shared__ float sc[NEXP];
    __shared__ float sb[NEXP];

    for (int i = tid; i < CDIM; i += 256) xs[i] = x[(size_t)t * CDIM + i];
    __syncthreads();

    int e = tid & 63, part = tid >> 6;
    float acc = 0.f;
    const float* rwp = rw + (size_t)(part * 256) * NEXP + e;
    #pragma unroll 8
    for (int c = 0; c < 256; c++) acc += xs[part * 256 + c] * rwp[(size_t)c * NEXP];
    partial[tid] = acc;
    __syncthreads();
    if (tid < NEXP) {
        float v = partial[tid] + partial[tid + 64] + partial[tid + 128] + partial[tid + 192];
        float s = 1.f / (1.f + __expf(-v));
        sc[tid] = s;
        sb[tid] = s + bias[tid];
    }
    __syncthreads();

    if (tid < 32) {
        float v0 = sb[tid], v1 = sb[tid + 32];
        int eid = 0;
        #pragma unroll
        for (int k = 0; k < TOPK; k++) {
            float m; int me;
            if (v0 >= v1) { m = v0; me = tid; } else { m = v1; me = tid + 32; }
            #pragma unroll
            for (int off = 16; off; off >>= 1) {
                float om = __shfl_down_sync(0xffffffffu, m, off);
                int   oe = __shfl_down_sync(0xffffffffu, me, off);
                if (om > m) { m = om; me = oe; }
            }
            me = __shfl_sync(0xffffffffu, me, 0);
            if (tid == me) v0 = -1e30f;
            if (tid == me - 32) v1 = -1e30f;
            if (tid == k) eid = me;
        }
        float sv = (tid < TOPK) ? sc[eid] : 0.f;
        float ws = sv;
        #pragma unroll
        for (int off = 4; off; off >>= 1) ws += __shfl_down_sync(0xffffffffu, ws, off, 8);
        ws = __shfl_sync(0xffffffffu, ws, 0);
        if (tid < TOPK) {
            int pos  = atomicAdd(&counts[eid], 1);
            int slot = eid * CAP + pos;
            rowidx[slot] = t;
            slots[t * TOPK + tid] = slot;
            wts  [t * TOPK + tid] = sv / ws;
        }
    }

    for (int i = tid; i < CDIM; i += 256)
        xr[(size_t)t * CDIM + i] = to_tf32(xs[i]);
}

// ---------------- tf32 mma.sync GEMM: D[M,N] = A[M,K] @ Bt[N,K]^T ----------------
// CTA tile 128x128, 8 warps of 64x32, Kc=32, 3-stage ring, 2 CTAs/SM.
// Smem: A 128x144B = 18432, B 128x144B = 18432; stage = 36864; 3 stages = 110592.
#define ROWB 144
#define A_BYTES 18432
#define STG_BYTES 36864

__device__ __forceinline__ void issue_stage(
    uint32_t sdst, const float* __restrict__ pA, const float* __restrict__ pB,
    int K, int kcol, int tid, const int* ar) {
    #pragma unroll
    for (int i = 0; i < 4; i++) {
        int id = tid + 256 * i;
        int row = id >> 3, c4 = id & 7;
        uint32_t so = (uint32_t)(row * ROWB + c4 * 16);
        CP_ASYNC16(sdst + so, pA + (size_t)ar[i] * K + kcol + c4 * 4);
        CP_ASYNC16(sdst + A_BYTES + so, pB + (size_t)row * K + kcol + c4 * 4);
    }
}

__global__ __launch_bounds__(256, 2) void gemm_kernel(
    const float* __restrict__ A, const float* __restrict__ B,
    float* __restrict__ D, float* __restrict__ H,
    int M, int N, int K,
    long sAz, long sBz, long sDz,
    const int* __restrict__ counts, const int* __restrict__ rowidx) {
    extern __shared__ __align__(128) char smem[];
    int z = blockIdx.z;
    if (counts) M = counts[z];
    int m0 = blockIdx.y * 128;
    if (m0 >= M) return;
    int n0 = blockIdx.x * 128;
    A += (size_t)z * sAz; B += (size_t)z * sBz;

    int tid = threadIdx.x, wid = tid >> 5, lane = tid & 31;
    int wm = (wid & 1) * 64;
    int wn = (wid >> 1) * 32;
    uint32_t sbase = smem_u32(smem);

    const float* pA;
    int ar[4];
    if (rowidx) {
        const int* ridx = rowidx + (size_t)z * CAP + m0;
        pA = A;
        #pragma unroll
        for (int i = 0; i < 4; i++) ar[i] = ridx[(tid >> 3) + 32 * i];
    } else {
        pA = A + (size_t)m0 * K;
        #pragma unroll
        for (int i = 0; i < 4; i++) ar[i] = (tid >> 3) + 32 * i;
    }
    const float* pB = B + (size_t)n0 * K;

    float acc[4][4][4];
    #pragma unroll
    for (int i = 0; i < 4; i++)
        #pragma unroll
        for (int j = 0; j < 4; j++)
            #pragma unroll
            for (int r = 0; r < 4; r++) acc[i][j][r] = 0.f;

    const int nk = K >> 5;
    issue_stage(sbase,             pA, pB, K, 0,  tid, ar); CP_COMMIT();
    issue_stage(sbase + STG_BYTES, pA, pB, K, 32, tid, ar); CP_COMMIT();

    // per-lane smem offsets (bytes)
    uint32_t aoff = (uint32_t)((wm + (lane & 15)) * ROWB + ((lane >> 4) & 1) * 16);
    uint32_t boff = (uint32_t)((wn + (lane & 7) + ((lane >> 4) & 1) * 8) * ROWB
                               + ((lane >> 3) & 1) * 16);

    int stg = 0;
    for (int kc = 0; kc < nk; kc++) {
        CP_WAIT1();
        __syncthreads();
        if (kc + 2 < nk) {
            int nx = stg + 2; if (nx >= 3) nx -= 3;
            issue_stage(sbase + nx * STG_BYTES, pA, pB, K, (kc + 2) * 32, tid, ar);
        }
        CP_COMMIT();

        uint32_t sA = sbase + stg * STG_BYTES;
        uint32_t sB = sA + A_BYTES;
        #pragma unroll
        for (int s = 0; s < 4; s++) {
            uint32_t a[4][4];
            #pragma unroll
            for (int mi = 0; mi < 4; mi++)
                ldm_x4(a[mi], sA + aoff + (uint32_t)(mi * 16 * ROWB + s * 32));
            #pragma unroll
            for (int j = 0; j < 2; j++) {
                uint32_t rb[4];
                ldm_x4(rb, sB + boff + (uint32_t)(j * 16 * ROWB + s * 32));
                #pragma unroll
                for (int mi = 0; mi < 4; mi++) {
                    mma_tf32(acc[mi][2 * j],     a[mi], rb);
                    mma_tf32(acc[mi][2 * j + 1], a[mi], rb + 2);
                }
            }
        }
        if (++stg == 3) stg = 0;
    }

    int r0 = lane >> 2, c0 = (lane & 3) * 2;
    if (H) {
        int halfN = N >> 1;
        H += (size_t)z * sDz;
        #pragma unroll
        for (int mi = 0; mi < 4; mi++) {
            #pragma unroll
            for (int ni = 0; ni < 4; ni++) {
                int row = m0 + wm + mi * 16 + r0;
                int p = (n0 + wn + ni * 8 + c0) >> 1;
                float y0 = acc[mi][ni][0], gg0 = acc[mi][ni][1];
                float y1 = acc[mi][ni][2], gg1 = acc[mi][ni][3];
                H[(size_t)row * halfN + p]       = to_tf32(y0 * gg0 / (1.f + __expf(-gg0)));
                H[(size_t)(row + 8) * halfN + p] = to_tf32(y1 * gg1 / (1.f + __expf(-gg1)));
            }
        }
    } else {
        D += (size_t)z * sDz;
        #pragma unroll
        for (int mi = 0; mi < 4; mi++) {
            #pragma unroll
            for (int ni = 0; ni < 4; ni++) {
                int row = m0 + wm + mi * 16 + r0;
                int col = n0 + wn + ni * 8 + c0;
                *(float2*)(D + (size_t)row * N + col) = make_float2(acc[mi][ni][0], acc[mi][ni][1]);
                *(float2*)(D + (size_t)(row + 8) * N + col) = make_float2(acc[mi][ni][2], acc[mi][ni][3]);
            }
        }
    }
}

// ---------------- combine ----------------
__global__ __launch_bounds__(256) void combine_kernel(
    const float* __restrict__ oe, const int* __restrict__ slots,
    const float* __restrict__ wts, float* __restrict__ out) {
    int t = blockIdx.x;
    int c = threadIdx.x * 4;
    int sl[TOPK]; float ww[TOPK];
    #pragma unroll
    for (int k = 0; k < TOPK; k++) { sl[k] = slots[t * TOPK + k]; ww[k] = wts[t * TOPK + k]; }
    float4 acc = *(float4*)(out + (size_t)t * CDIM + c);
    #pragma unroll
    for (int k = 0; k < TOPK; k++) {
        float4 v = *(const float4*)(oe + (size_t)sl[k] * CDIM + c);
        acc.x += ww[k] * v.x; acc.y += ww[k] * v.y;
        acc.z += ww[k] * v.z; acc.w += ww[k] * v.w;
    }
    *(float4*)(out + (size_t)t * CDIM + c) = acc;
}

// ---------------- launch ----------------
extern "C" void kernel_launch(void* const* d_in, const int* in_sizes, int n_in,
                              void* d_out, int out_size) {
    const float* x       = (const float*)d_in[0];
    const float* rw      = (const float*)d_in[1];
    const float* bias    = (const float*)d_in[2];
    const float* sup_w   = (const float*)d_in[3];
    const float* sdown_w = (const float*)d_in[4];
    const float* eup_w   = (const float*)d_in[5];
    const float* edown_w = (const float*)d_in[6];
    float* out = (float*)d_out;
    (void)in_sizes; (void)n_in; (void)out_size;

    float *xr, *sh, *eh, *eoe, *supt, *sdnt, *eupt, *ednt, *wts;
    int *counts, *rowidx, *slots;
    cudaGetSymbolAddress((void**)&xr, g_xr);
    cudaGetSymbolAddress((void**)&sh, g_sh);
    cudaGetSymbolAddress((void**)&eh, g_eh);
    cudaGetSymbolAddress((void**)&eoe, g_eoe);
    cudaGetSymbolAddress((void**)&supt, g_supt);
    cudaGetSymbolAddress((void**)&sdnt, g_sdnt);
    cudaGetSymbolAddress((void**)&eupt, g_eupt);
    cudaGetSymbolAddress((void**)&ednt, g_ednt);
    cudaGetSymbolAddress((void**)&counts, g_counts);
    cudaGetSymbolAddress((void**)&rowidx, g_rowidx);
    cudaGetSymbolAddress((void**)&slots, g_slots);
    cudaGetSymbolAddress((void**)&wts, g_wts);

    cudaFuncSetAttribute(gemm_kernel, cudaFuncAttributeMaxDynamicSharedMemorySize, 3 * STG_BYTES);
    const int gsmem = 3 * STG_BYTES;

    // 1. prep (counts zero + all transposes) and routing
    prep_kernel<<<dim3(64, 32, 130), dim3(32, 8)>>>(
        sup_w, sdown_w, eup_w, edown_w, supt, sdnt, eupt, ednt, counts);
    router_kernel<<<NTOK, 256>>>(x, rw, bias, counts, rowidx, slots, wts, xr);

    // 2. UP GEMMs (fused swiglu epilogue)
    gemm_kernel<<<dim3(2 * HE / 128, CAP / 128, NEXP), 256, gsmem>>>(
        xr, eupt, nullptr, eh, CAP, 2 * HE, CDIM,
        0, (long)(2 * HE) * CDIM, (long)CAP * HE, counts, rowidx);
    gemm_kernel<<<dim3(2 * HS / 128, NTOK / 128, 1), 256, gsmem>>>(
        xr, supt, nullptr, sh, NTOK, 2 * HS, CDIM, 0, 0, 0, nullptr, nullptr);

    // 3. DOWN GEMMs
    gemm_kernel<<<dim3(CDIM / 128, CAP / 128, NEXP), 256, gsmem>>>(
        eh, ednt, eoe, nullptr, CAP, CDIM, HE,
        (long)CAP * HE, (long)CDIM * HE, (long)CAP * CDIM, counts, nullptr);
    gemm_kernel<<<dim3(CDIM / 128, NTOK / 128, 1), 256, gsmem>>>(
        sh, sdnt, out, nullptr, NTOK, CDIM, HS, 0, 0, 0, nullptr, nullptr);

    // 4. combine
    combine_kernel<<<NTOK, 256>>>(eoe, slots, wts, out);
}

// round 11
// speedup vs baseline: 1.1568x; 1.0678x over previous
#include <cuda_runtime.h>
#include <cuda_bf16.h>
#include <cstdint>

// ---------------- shapes ----------------
#define NTOK 4096
#define CDIM 1024
#define NEXP 64
#define TOPK 8
#define CAP  1024
#define HS   1024
#define HE   512

// ---------------- helpers ----------------
__device__ __forceinline__ uint32_t smem_u32(const void* p) {
    uint32_t a;
    asm("{ .reg .u64 t; cvta.to.shared.u64 t, %1; cvt.u32.u64 %0, t; }" : "=r"(a) : "l"(p));
    return a;
}
#define CP_ASYNC16(dst, src) \
    asm volatile("cp.async.cg.shared.global [%0], [%1], 16;" :: "r"(dst), "l"(src))
#define CP_COMMIT() asm volatile("cp.async.commit_group;" ::: "memory")
#define CP_WAIT1()  asm volatile("cp.async.wait_group 1;" ::: "memory")

__device__ __forceinline__ void ldm_x4(uint32_t* r, uint32_t addr) {
    asm volatile("ldmatrix.sync.aligned.m8n8.x4.shared.b16 {%0,%1,%2,%3}, [%4];"
        : "=r"(r[0]), "=r"(r[1]), "=r"(r[2]), "=r"(r[3]) : "r"(addr));
}
__device__ __forceinline__ void mma_tf32(float* d, const uint32_t* a, const uint32_t* b) {
    asm volatile(
        "mma.sync.aligned.m16n8k8.row.col.f32.tf32.tf32.f32 "
        "{%0,%1,%2,%3}, {%4,%5,%6,%7}, {%8,%9}, {%0,%1,%2,%3};"
        : "+f"(d[0]), "+f"(d[1]), "+f"(d[2]), "+f"(d[3])
        : "r"(a[0]), "r"(a[1]), "r"(a[2]), "r"(a[3]), "r"(b[0]), "r"(b[1]));
}
__device__ __forceinline__ float to_tf32(float v) {
    uint32_t r;
    asm("cvt.rna.tf32.f32 %0, %1;" : "=r"(r) : "f"(v));
    return __uint_as_float(r);
}

// ---------------- scratch (device globals) ----------------
__device__ float g_xr  [(size_t)NTOK * CDIM];
__device__ float g_sh  [(size_t)NTOK * HS];
__device__ float g_eh  [(size_t)NEXP * CAP * HE];
__device__ float g_eoe [(size_t)NEXP * CAP * CDIM];
__device__ float g_supt[(size_t)(2 * HS) * CDIM];
__device__ float g_sdnt[(size_t)CDIM * HS];
__device__ float g_eupt[(size_t)NEXP * (2 * HE) * CDIM];
__device__ float g_ednt[(size_t)NEXP * CDIM * HE];
__device__ int   g_counts[NEXP];
__device__ int   g_rowidx[NEXP * CAP];
__device__ int   g_slots[NTOK * TOPK];
__device__ float g_wts [NTOK * TOPK];

// ---------------- zero counts (tiny, runs before router on its stream) ----------------
__global__ void zero_counts_kernel(int* counts) {
    if (threadIdx.x < NEXP) counts[threadIdx.x] = 0;
}

// ---------------- fused prep: all 4 weight transposes ----------------
__global__ void prep_kernel(const float* __restrict__ sup_w, const float* __restrict__ sdown_w,
                            const float* __restrict__ eup_w, const float* __restrict__ edown_w,
                            float* __restrict__ supt, float* __restrict__ sdnt,
                            float* __restrict__ eupt, float* __restrict__ ednt) {
    __shared__ float tile[32][33];
    int z = blockIdx.z;
    const float* in; float* o;
    int K, N, half, nx, ny;
    size_t inoff = 0, outoff = 0;
    if (z < 64) {
        in = eup_w; o = eupt; K = CDIM; N = 2 * HE; half = HE; nx = 32; ny = 32;
        inoff = (size_t)z * CDIM * 2 * HE; outoff = (size_t)z * 2 * HE * CDIM;
    } else if (z < 128) {
        int zz = z - 64;
        in = edown_w; o = ednt; K = HE; N = CDIM; half = 0; nx = 32; ny = 16;
        inoff = (size_t)zz * HE * CDIM; outoff = (size_t)zz * CDIM * HE;
    } else if (z == 128) {
        in = sup_w; o = supt; K = CDIM; N = 2 * HS; half = HS; nx = 64; ny = 32;
    } else {
        in = sdown_w; o = sdnt; K = HS; N = CDIM; half = 0; nx = 32; ny = 32;
    }
    if ((int)blockIdx.x >= nx || (int)blockIdx.y >= ny) return;
    in += inoff; o += outoff;
    int n0 = blockIdx.x * 32, k0 = blockIdx.y * 32;
    int tx = threadIdx.x, ty = threadIdx.y;
    #pragma unroll
    for (int i = 0; i < 32; i += 8)
        tile[ty + i][tx] = in[(size_t)(k0 + ty + i) * N + n0 + tx];
    __syncthreads();
    #pragma unroll
    for (int i = 0; i < 32; i += 8) {
        float v = tile[tx][ty + i];
        int n = n0 + ty + i;
        int nout = (half > 0) ? ((n < half) ? 2 * n : 2 * (n - half) + 1) : n;
        o[(size_t)nout * K + k0 + tx] = to_tf32(v);
    }
}

// ---------------- router ----------------
__global__ __launch_bounds__(256) void router_kernel(
    const float* __restrict__ x, const float* __restrict__ rw, const float* __restrict__ bias,
    int* __restrict__ counts, int* __restrict__ rowidx,
    int* __restrict__ slots, float* __restrict__ wts, float* __restrict__ xr) {
    int t = blockIdx.x;
    int tid = threadIdx.x;
    __shared__ float xs[CDIM];
    __shared__ float partial[256];
    __shared__ float sc[NEXP];
    __shared__ float sb[NEXP];

    for (int i = tid; i < CDIM; i += 256) xs[i] = x[(size_t)t * CDIM + i];
    __syncthreads();

    int e = tid & 63, part = tid >> 6;
    float acc = 0.f;
    const float* rwp = rw + (size_t)(part * 256) * NEXP + e;
    #pragma unroll 8
    for (int c = 0; c < 256; c++) acc += xs[part * 256 + c] * rwp[(size_t)c * NEXP];
    partial[tid] = acc;
    __syncthreads();
    if (tid < NEXP) {
        float v = partial[tid] + partial[tid + 64] + partial[tid + 128] + partial[tid + 192];
        float s = 1.f / (1.f + __expf(-v));
        sc[tid] = s;
        sb[tid] = s + bias[tid];
    }
    __syncthreads();

    if (tid < 32) {
        float v0 = sb[tid], v1 = sb[tid + 32];
        int eid = 0;
        #pragma unroll
        for (int k = 0; k < TOPK; k++) {
            float m; int me;
            if (v0 >= v1) { m = v0; me = tid; } else { m = v1; me = tid + 32; }
            #pragma unroll
            for (int off = 16; off; off >>= 1) {
                float om = __shfl_down_sync(0xffffffffu, m, off);
                int   oe = __shfl_down_sync(0xffffffffu, me, off);
                if (om > m) { m = om; me = oe; }
            }
            me = __shfl_sync(0xffffffffu, me, 0);
            if (tid == me) v0 = -1e30f;
            if (tid == me - 32) v1 = -1e30f;
            if (tid == k) eid = me;
        }
        float sv = (tid < TOPK) ? sc[eid] : 0.f;
        float ws = sv;
        #pragma unroll
        for (int off = 4; off; off >>= 1) ws += __shfl_down_sync(0xffffffffu, ws, off, 8);
        ws = __shfl_sync(0xffffffffu, ws, 0);
        if (tid < TOPK) {
            int pos  = atomicAdd(&counts[eid], 1);
            int slot = eid * CAP + pos;
            rowidx[slot] = t;
            slots[t * TOPK + tid] = slot;
            wts  [t * TOPK + tid] = sv / ws;
        }
    }

    for (int i = tid; i < CDIM; i += 256)
        xr[(size_t)t * CDIM + i] = to_tf32(xs[i]);
}

// ---------------- tf32 mma.sync GEMM: D[M,N] = A[M,K] @ Bt[N,K]^T ----------------
// CTA tile 128x128, 8 warps of 64x32, Kc=32, 3-stage ring, 2 CTAs/SM.
#define ROWB 144
#define A_BYTES 18432
#define STG_BYTES 36864

__device__ __forceinline__ void issue_stage(
    uint32_t sdst, const float* __restrict__ pA, const float* __restrict__ pB,
    int K, int kcol, int tid, const int* ar) {
    #pragma unroll
    for (int i = 0; i < 4; i++) {
        int id = tid + 256 * i;
        int row = id >> 3, c4 = id & 7;
        uint32_t so = (uint32_t)(row * ROWB + c4 * 16);
        CP_ASYNC16(sdst + so, pA + (size_t)ar[i] * K + kcol + c4 * 4);
        CP_ASYNC16(sdst + A_BYTES + so, pB + (size_t)row * K + kcol + c4 * 4);
    }
}

__global__ __launch_bounds__(256, 2) void gemm_kernel(
    const float* __restrict__ A, const float* __restrict__ B,
    float* __restrict__ D, float* __restrict__ H,
    int M, int N, int K,
    long sAz, long sBz, long sDz,
    const int* __restrict__ counts, const int* __restrict__ rowidx) {
    extern __shared__ __align__(128) char smem[];
    int z = blockIdx.z;
    if (counts) M = counts[z];
    int m0 = blockIdx.y * 128;
    if (m0 >= M) return;
    int n0 = blockIdx.x * 128;
    A += (size_t)z * sAz; B += (size_t)z * sBz;

    int tid = threadIdx.x, wid = tid >> 5, lane = tid & 31;
    int wm = (wid & 1) * 64;
    int wn = (wid >> 1) * 32;
    uint32_t sbase = smem_u32(smem);

    const float* pA;
    int ar[4];
    if (rowidx) {
        const int* ridx = rowidx + (size_t)z * CAP + m0;
        pA = A;
        #pragma unroll
        for (int i = 0; i < 4; i++) ar[i] = ridx[(tid >> 3) + 32 * i];
    } else {
        pA = A + (size_t)m0 * K;
        #pragma unroll
        for (int i = 0; i < 4; i++) ar[i] = (tid >> 3) + 32 * i;
    }
    const float* pB = B + (size_t)n0 * K;

    float acc[4][4][4];
    #pragma unroll
    for (int i = 0; i < 4; i++)
        #pragma unroll
        for (int j = 0; j < 4; j++)
            #pragma unroll
            for (int r = 0; r < 4; r++) acc[i][j][r] = 0.f;

    const int nk = K >> 5;
    issue_stage(sbase,             pA, pB, K, 0,  tid, ar); CP_COMMIT();
    issue_stage(sbase + STG_BYTES, pA, pB, K, 32, tid, ar); CP_COMMIT();

    uint32_t aoff = (uint32_t)((wm + (lane & 15)) * ROWB + ((lane >> 4) & 1) * 16);
    uint32_t boff = (uint32_t)((wn + (lane & 7) + ((lane >> 4) & 1) * 8) * ROWB
                               + ((lane >> 3) & 1) * 16);

    int stg = 0;
    for (int kc = 0; kc < nk; kc++) {
        CP_WAIT1();
        __syncthreads();
        if (kc + 2 < nk) {
            int nx = stg + 2; if (nx >= 3) nx -= 3;
            issue_stage(sbase + nx * STG_BYTES, pA, pB, K, (kc + 2) * 32, tid, ar);
        }
        CP_COMMIT();

        uint32_t sA = sbase + stg * STG_BYTES;
        uint32_t sB = sA + A_BYTES;
        #pragma unroll
        for (int s = 0; s < 4; s++) {
            uint32_t a[4][4];
            #pragma unroll
            for (int mi = 0; mi < 4; mi++)
                ldm_x4(a[mi], sA + aoff + (uint32_t)(mi * 16 * ROWB + s * 32));
            #pragma unroll
            for (int j = 0; j < 2; j++) {
                uint32_t rb[4];
                ldm_x4(rb, sB + boff + (uint32_t)(j * 16 * ROWB + s * 32));
                #pragma unroll
                for (int mi = 0; mi < 4; mi++) {
                    mma_tf32(acc[mi][2 * j],     a[mi], rb);
                    mma_tf32(acc[mi][2 * j + 1], a[mi], rb + 2);
                }
            }
        }
        if (++stg == 3) stg = 0;
    }

    int r0 = lane >> 2, c0 = (lane & 3) * 2;
    if (H) {
        int halfN = N >> 1;
        H += (size_t)z * sDz;
        #pragma unroll
        for (int mi = 0; mi < 4; mi++) {
            #pragma unroll
            for (int ni = 0; ni < 4; ni++) {
                int row = m0 + wm + mi * 16 + r0;
                int p = (n0 + wn + ni * 8 + c0) >> 1;
                float y0 = acc[mi][ni][0], gg0 = acc[mi][ni][1];
                float y1 = acc[mi][ni][2], gg1 = acc[mi][ni][3];
                H[(size_t)row * halfN + p]       = to_tf32(y0 * gg0 / (1.f + __expf(-gg0)));
                H[(size_t)(row + 8) * halfN + p] = to_tf32(y1 * gg1 / (1.f + __expf(-gg1)));
            }
        }
    } else {
        D += (size_t)z * sDz;
        #pragma unroll
        for (int mi = 0; mi < 4; mi++) {
            #pragma unroll
            for (int ni = 0; ni < 4; ni++) {
                int row = m0 + wm + mi * 16 + r0;
                int col = n0 + wn + ni * 8 + c0;
                *(float2*)(D + (size_t)row * N + col) = make_float2(acc[mi][ni][0], acc[mi][ni][1]);
                *(float2*)(D + (size_t)(row + 8) * N + col) = make_float2(acc[mi][ni][2], acc[mi][ni][3]);
            }
        }
    }
}

// ---------------- combine ----------------
__global__ __launch_bounds__(256) void combine_kernel(
    const float* __restrict__ oe, const int* __restrict__ slots,
    const float* __restrict__ wts, float* __restrict__ out) {
    int t = blockIdx.x;
    int c = threadIdx.x * 4;
    int sl[TOPK]; float ww[TOPK];
    #pragma unroll
    for (int k = 0; k < TOPK; k++) { sl[k] = slots[t * TOPK + k]; ww[k] = wts[t * TOPK + k]; }
    float4 acc = *(float4*)(out + (size_t)t * CDIM + c);
    #pragma unroll
    for (int k = 0; k < TOPK; k++) {
        float4 v = *(const float4*)(oe + (size_t)sl[k] * CDIM + c);
        acc.x += ww[k] * v.x; acc.y += ww[k] * v.y;
        acc.z += ww[k] * v.z; acc.w += ww[k] * v.w;
    }
    *(float4*)(out + (size_t)t * CDIM + c) = acc;
}

// ---------------- launch (two-stream DAG, graph-capturable fork/join) ----------------
extern "C" void kernel_launch(void* const* d_in, const int* in_sizes, int n_in,
                              void* d_out, int out_size) {
    const float* x       = (const float*)d_in[0];
    const float* rw      = (const float*)d_in[1];
    const float* bias    = (const float*)d_in[2];
    const float* sup_w   = (const float*)d_in[3];
    const float* sdown_w = (const float*)d_in[4];
    const float* eup_w   = (const float*)d_in[5];
    const float* edown_w = (const float*)d_in[6];
    float* out = (float*)d_out;
    (void)in_sizes; (void)n_in; (void)out_size;

    float *xr, *sh, *eh, *eoe, *supt, *sdnt, *eupt, *ednt, *wts;
    int *counts, *rowidx, *slots;
    cudaGetSymbolAddress((void**)&xr, g_xr);
    cudaGetSymbolAddress((void**)&sh, g_sh);
    cudaGetSymbolAddress((void**)&eh, g_eh);
    cudaGetSymbolAddress((void**)&eoe, g_eoe);
    cudaGetSymbolAddress((void**)&supt, g_supt);
    cudaGetSymbolAddress((void**)&sdnt, g_sdnt);
    cudaGetSymbolAddress((void**)&eupt, g_eupt);
    cudaGetSymbolAddress((void**)&ednt, g_ednt);
    cudaGetSymbolAddress((void**)&counts, g_counts);
    cudaGetSymbolAddress((void**)&rowidx, g_rowidx);
    cudaGetSymbolAddress((void**)&slots, g_slots);
    cudaGetSymbolAddress((void**)&wts, g_wts);

    cudaFuncSetAttribute(gemm_kernel, cudaFuncAttributeMaxDynamicSharedMemorySize, 3 * STG_BYTES);
    const int gsmem = 3 * STG_BYTES;

    // one-time side stream + fork/join events (host-side objects only; no device memory)
    static cudaStream_t s1 = nullptr;
    static cudaEvent_t evFork0 = nullptr, evJoin0 = nullptr, evFork1 = nullptr, evJoin1 = nullptr;
    if (!s1) {
        cudaStreamCreateWithFlags(&s1, cudaStreamNonBlocking);
        cudaEventCreateWithFlags(&evFork0, cudaEventDisableTiming);
        cudaEventCreateWithFlags(&evJoin0, cudaEventDisableTiming);
        cudaEventCreateWithFlags(&evFork1, cudaEventDisableTiming);
        cudaEventCreateWithFlags(&evJoin1, cudaEventDisableTiming);
    }

    // ---- fork: router chain on s1, prep on main ----
    cudaEventRecord(evFork0, 0);
    cudaStreamWaitEvent(s1, evFork0, 0);

    zero_counts_kernel<<<1, 64, 0, s1>>>(counts);
    router_kernel<<<NTOK, 256, 0, s1>>>(x, rw, bias, counts, rowidx, slots, wts, xr);

    prep_kernel<<<dim3(64, 32, 130), dim3(32, 8)>>>(
        sup_w, sdown_w, eup_w, edown_w, supt, sdnt, eupt, ednt);

    // ---- join (GEMMs need both), then fork: expert chain on main, shared chain on s1 ----
    cudaEventRecord(evJoin0, s1);
    cudaStreamWaitEvent(0, evJoin0, 0);
    cudaEventRecord(evFork1, 0);
    cudaStreamWaitEvent(s1, evFork1, 0);

    // main: expert-up -> expert-down
    gemm_kernel<<<dim3(2 * HE / 128, CAP / 128, NEXP), 256, gsmem>>>(
        xr, eupt, nullptr, eh, CAP, 2 * HE, CDIM,
        0, (long)(2 * HE) * CDIM, (long)CAP * HE, counts, rowidx);
    gemm_kernel<<<dim3(CDIM / 128, CAP / 128, NEXP), 256, gsmem>>>(
        eh, ednt, eoe, nullptr, CAP, CDIM, HE,
        (long)CAP * HE, (long)CDIM * HE, (long)CAP * CDIM, counts, nullptr);

    // s1: shared-up -> shared-down (writes out)
    gemm_kernel<<<dim3(2 * HS / 128, NTOK / 128, 1), 256, gsmem, s1>>>(
        xr, supt, nullptr, sh, NTOK, 2 * HS, CDIM, 0, 0, 0, nullptr, nullptr);
    gemm_kernel<<<dim3(CDIM / 128, NTOK / 128, 1), 256, gsmem, s1>>>(
        sh, sdnt, out, nullptr, NTOK, CDIM, HS, 0, 0, 0, nullptr, nullptr);

    // ---- join, then combine ----
    cudaEventRecord(evJoin1, s1);
    cudaStreamWaitEvent(0, evJoin1, 0);

    combine_kernel<<<NTOK, 256>>>(eoe, slots, wts, out);
}